// round 3
// baseline (speedup 1.0000x reference)
#include <cuda_runtime.h>
#include <math.h>

// ---------------------------------------------------------------------------
// KoopmanPhiICNN encode: 64 Adam steps minimizing ICNN energy over z slice.
// fp32 SIMT GEMMs (128x64x16 tiles, smem double-buffered), fused epilogues.
// Per step: fwd0, fwd1, fwd2, fwd3(->d3), bwd2(->d2,g), bwd1, bwd0, bwdin+Adam.
// Constants c_in / c_x (frozen [x|u] contributions) and softplus(Wzs)
// hoisted out of the step loop.
// R2 fix: mm_nn prologue no longer zero-fills Bs (smem write race).
// ---------------------------------------------------------------------------

#define Bsz 4096
#define Hd  832
#define Zd  256
#define BH  (Bsz*Hd)     // 3,407,872
#define HH  (Hd*Hd)      //   692,224
#define BZ  (Bsz*Zd)     // 1,048,576
#define NSTEPS 64

#define BM 128
#define BN 64
#define BK 16
#define NTHR 256

// ---- scratch layout in one big device array (alloc-free rule) ----
#define O_SWZ  0ull
#define O_SWZO (O_SWZ + 3ull*HH)
#define O_C    (O_SWZO + 832ull)
#define O_H    (O_C   + 4ull*BH)
#define O_DA   (O_H   + 3ull*BH)
#define O_DB   (O_DA  + (unsigned long long)BH)
#define O_G    (O_DB  + (unsigned long long)BH)
#define O_M    (O_G   + (unsigned long long)BZ)
#define O_V    (O_M   + (unsigned long long)BZ)
#define TOTALF (O_V   + (unsigned long long)BZ)

__device__ __align__(16) float g_buf[TOTALF];

__device__ __forceinline__ float sp_(float x) {
    // stable softplus: max(x,0) + log1p(exp(-|x|))
    return fmaxf(x, 0.f) + log1pf(expf(-fabsf(x)));
}
__device__ __forceinline__ float sig_(float x) {
    return 1.f / (1.f + expf(-x));
}
// sigmoid(a) given h = softplus(a):  s = 1 - e^{-h}
__device__ __forceinline__ float sig_from_h(float h) {
    return -expm1f(-h);
}

// ---------------------------------------------------------------------------
// GEMM cores. acc[8][4] per thread; block computes 128x64 of C.
// NT: C[m,n] = sum_k A[m,k]*B[n,k]   (both row-major)
// NN: C[m,n] = sum_k A[m,k]*B[k,n]
// ---------------------------------------------------------------------------

__device__ __forceinline__ void mm_compute(float acc[8][4],
    const float As[BK][BM + 4], const float Bs[BK][BN], int tx, int ty)
{
#pragma unroll
    for (int kk = 0; kk < BK; kk++) {
        float4 a0 = *reinterpret_cast<const float4*>(&As[kk][ty * 8]);
        float4 a1 = *reinterpret_cast<const float4*>(&As[kk][ty * 8 + 4]);
        float4 b  = *reinterpret_cast<const float4*>(&Bs[kk][tx * 4]);
        float av[8] = {a0.x, a0.y, a0.z, a0.w, a1.x, a1.y, a1.z, a1.w};
        float bv[4] = {b.x, b.y, b.z, b.w};
#pragma unroll
        for (int i = 0; i < 8; i++)
#pragma unroll
            for (int j = 0; j < 4; j++)
                acc[i][j] = fmaf(av[i], bv[j], acc[i][j]);
    }
}

__device__ __forceinline__ void st_a(float As[BK][BM + 4],
                                     int r, int c, float4 va0, float4 va1)
{
    As[c + 0][r] = va0.x; As[c + 1][r] = va0.y; As[c + 2][r] = va0.z; As[c + 3][r] = va0.w;
    As[c + 0][r + 64] = va1.x; As[c + 1][r + 64] = va1.y; As[c + 2][r + 64] = va1.z; As[c + 3][r + 64] = va1.w;
}

__device__ __forceinline__ void st_nt(float As[BK][BM + 4], float Bs[BK][BN],
                                      int r, int c, float4 va0, float4 va1, float4 vb)
{
    st_a(As, r, c, va0, va1);
    Bs[c + 0][r] = vb.x; Bs[c + 1][r] = vb.y; Bs[c + 2][r] = vb.z; Bs[c + 3][r] = vb.w;
}

// A row-major [M,K] lda; B row-major [N,K] ldb. kt = K/BK tiles.
__device__ __forceinline__ void mm_nt(float acc[8][4],
    const float* __restrict__ A, int lda,
    const float* __restrict__ Bm, int ldb, int kt,
    int m0, int n0, int tid, int tx, int ty,
    float (&As)[2][BK][BM + 4], float (&Bs)[2][BK][BN])
{
    const int r = tid >> 2;
    const int c = (tid & 3) * 4;
    const float* Ap0 = A + (size_t)(m0 + r) * lda + c;
    const float* Ap1 = A + (size_t)(m0 + r + 64) * lda + c;
    const float* Bp  = Bm + (size_t)(n0 + r) * ldb + c;

    float4 va0 = *reinterpret_cast<const float4*>(Ap0);
    float4 va1 = *reinterpret_cast<const float4*>(Ap1);
    float4 vb  = *reinterpret_cast<const float4*>(Bp);
    __syncthreads();                 // previous users of smem done
    st_nt(As[0], Bs[0], r, c, va0, va1, vb);
    __syncthreads();

    for (int t = 0; t < kt; t++) {
        int buf = t & 1;
        if (t + 1 < kt) {
            va0 = *reinterpret_cast<const float4*>(Ap0 + (t + 1) * BK);
            va1 = *reinterpret_cast<const float4*>(Ap1 + (t + 1) * BK);
            vb  = *reinterpret_cast<const float4*>(Bp  + (t + 1) * BK);
        }
        mm_compute(acc, As[buf], Bs[buf], tx, ty);
        if (t + 1 < kt) st_nt(As[buf ^ 1], Bs[buf ^ 1], r, c, va0, va1, vb);
        __syncthreads();
    }
}

// A row-major [M,K] lda; B element (k, n_local) = Bm[k*ldb + n_local]
// (caller pre-offsets Bm to the starting column). kt = K/BK.
__device__ __forceinline__ void mm_nn(float acc[8][4],
    const float* __restrict__ A, int lda,
    const float* __restrict__ Bm, int ldb, int kt,
    int m0, int tid, int tx, int ty,
    float (&As)[2][BK][BM + 4], float (&Bs)[2][BK][BN])
{
    const int r  = tid >> 2;
    const int c  = (tid & 3) * 4;
    const int rb = tid >> 4;          // k row within tile (0..15)
    const int cb = (tid & 15) * 4;    // n col (0..60)
    const float* Ap0 = A + (size_t)(m0 + r) * lda + c;
    const float* Ap1 = A + (size_t)(m0 + r + 64) * lda + c;
    const float* Bp  = Bm + (size_t)rb * ldb + cb;

    float4 va0 = *reinterpret_cast<const float4*>(Ap0);
    float4 va1 = *reinterpret_cast<const float4*>(Ap1);
    float4 vb  = *reinterpret_cast<const float4*>(Bp);
    __syncthreads();
    st_a(As[0], r, c, va0, va1);                      // A only — no Bs zero-fill
    *reinterpret_cast<float4*>(&Bs[0][rb][cb]) = vb;  // each thread owns its slot
    __syncthreads();

    for (int t = 0; t < kt; t++) {
        int buf = t & 1;
        if (t + 1 < kt) {
            va0 = *reinterpret_cast<const float4*>(Ap0 + (t + 1) * BK);
            va1 = *reinterpret_cast<const float4*>(Ap1 + (t + 1) * BK);
            vb  = *reinterpret_cast<const float4*>(Bp + (size_t)(t + 1) * BK * ldb);
        }
        mm_compute(acc, As[buf], Bs[buf], tx, ty);
        if (t + 1 < kt) {
            int nb = buf ^ 1;
            st_a(As[nb], r, c, va0, va1);
            *reinterpret_cast<float4*>(&Bs[nb][rb][cb]) = vb;
        }
        __syncthreads();
    }
}

// ---------------------------------------------------------------------------
// Kernels
// ---------------------------------------------------------------------------

// Precompute: SWz = softplus(Wzs), swz_out = softplus(wz_out); zero z, m, v.
__global__ void kprep(const float* __restrict__ Wzs, const float* __restrict__ wz_out,
                      float* __restrict__ Z)
{
    float* SWZ  = g_buf + O_SWZ;
    float* SWZO = g_buf + O_SWZO;
    float* Mm   = g_buf + O_M;
    float* Vv   = g_buf + O_V;
    const int n = 3 * HH;
    for (int i = blockIdx.x * blockDim.x + threadIdx.x; i < n;
         i += gridDim.x * blockDim.x) {
        SWZ[i] = sp_(Wzs[i]);
        if (i < Hd) SWZO[i] = sp_(wz_out[i]);
        if (i < BZ) { Z[i] = 0.f; Mm[i] = 0.f; Vv[i] = 0.f; }
    }
}

// c[s] = [x|u] @ W_s[:,256:]^T + bias_s   (s=0: W_in/b_in, s=1..3: Wxs/bs)
__global__ void __launch_bounds__(NTHR) kpre(
    const float* __restrict__ x, const float* __restrict__ u,
    const float* __restrict__ W_in, const float* __restrict__ b_in,
    const float* __restrict__ Wxs, const float* __restrict__ bs)
{
    __shared__ float As[2][BK][BM + 4];
    __shared__ float Bs[2][BK][BN];
    const int tid = threadIdx.x, tx = tid & 15, ty = tid >> 4;
    const int m0 = blockIdx.y * BM, n0 = blockIdx.x * BN;
    const int s = blockIdx.z;
    const float* W    = (s == 0) ? W_in : Wxs + (size_t)(s - 1) * HH;
    const float* bias = (s == 0) ? b_in : bs + (size_t)(s - 1) * Hd;
    float* Out = g_buf + O_C + (size_t)s * BH;

    float acc[8][4];
#pragma unroll
    for (int i = 0; i < 8; i++)
#pragma unroll
        for (int j = 0; j < 4; j++) acc[i][j] = 0.f;

    const int r = tid >> 2;
    const int c = (tid & 3) * 4;
    const int kt = 576 / BK;  // 36 tiles over [x(512) | u(64)]
    const float* Bp = W + (size_t)(n0 + r) * Hd + 256 + c;

    // prologue
    float4 va0, va1, vb;
    {
        int k = c;
        va0 = *reinterpret_cast<const float4*>(&x[(size_t)(m0 + r) * 512 + k]);
        va1 = *reinterpret_cast<const float4*>(&x[(size_t)(m0 + r + 64) * 512 + k]);
        vb  = *reinterpret_cast<const float4*>(Bp);
    }
    __syncthreads();
    st_nt(As[0], Bs[0], r, c, va0, va1, vb);
    __syncthreads();

    for (int t = 0; t < kt; t++) {
        int buf = t & 1;
        if (t + 1 < kt) {
            int k = (t + 1) * BK + c;
            if (k < 512) {
                va0 = *reinterpret_cast<const float4*>(&x[(size_t)(m0 + r) * 512 + k]);
                va1 = *reinterpret_cast<const float4*>(&x[(size_t)(m0 + r + 64) * 512 + k]);
            } else {
                va0 = *reinterpret_cast<const float4*>(&u[(size_t)(m0 + r) * 64 + (k - 512)]);
                va1 = *reinterpret_cast<const float4*>(&u[(size_t)(m0 + r + 64) * 64 + (k - 512)]);
            }
            vb = *reinterpret_cast<const float4*>(Bp + (t + 1) * BK);
        }
        mm_compute(acc, As[buf], Bs[buf], tx, ty);
        if (t + 1 < kt) st_nt(As[buf ^ 1], Bs[buf ^ 1], r, c, va0, va1, vb);
        __syncthreads();
    }

    const float4 b4 = *reinterpret_cast<const float4*>(&bias[n0 + tx * 4]);
#pragma unroll
    for (int i = 0; i < 8; i++) {
        int m = m0 + ty * 8 + i;
        float4 o;
        o.x = acc[i][0] + b4.x; o.y = acc[i][1] + b4.y;
        o.z = acc[i][2] + b4.z; o.w = acc[i][3] + b4.w;
        *reinterpret_cast<float4*>(&Out[(size_t)m * Hd + n0 + tx * 4]) = o;
    }
}

// Forward layer. MODE 0: input layer (h0 = sp(z@Win_z^T + c_in))
//               MODE 1: hidden     (h  = sp(hprev@SWz^T + z@Wx_z^T + c))
//               MODE 2: hidden+final (emit d3 = swz_out * sigmoid(a3))
template<int MODE>
__global__ void __launch_bounds__(NTHR) kfwd(
    const float* __restrict__ A1, const float* __restrict__ B1,
    const float* __restrict__ A2, const float* __restrict__ B2,
    const float* __restrict__ C0, float* __restrict__ Out)
{
    __shared__ float As[2][BK][BM + 4];
    __shared__ float Bs[2][BK][BN];
    const int tid = threadIdx.x, tx = tid & 15, ty = tid >> 4;
    const int m0 = blockIdx.y * BM, n0 = blockIdx.x * BN;

    float acc[8][4];
#pragma unroll
    for (int i = 0; i < 8; i++)
#pragma unroll
        for (int j = 0; j < 4; j++) acc[i][j] = 0.f;

    if (MODE == 0) {
        mm_nt(acc, A1, Zd, B1, Hd, Zd / BK, m0, n0, tid, tx, ty, As, Bs);
    } else {
        mm_nt(acc, A1, Hd, B1, Hd, Hd / BK, m0, n0, tid, tx, ty, As, Bs);
        mm_nt(acc, A2, Zd, B2, Hd, Zd / BK, m0, n0, tid, tx, ty, As, Bs);
    }

    const float* SWZO = g_buf + O_SWZO;
    float4 s4;
    if (MODE == 2) s4 = *reinterpret_cast<const float4*>(&SWZO[n0 + tx * 4]);
#pragma unroll
    for (int i = 0; i < 8; i++) {
        int m = m0 + ty * 8 + i;
        const float4 c4 = *reinterpret_cast<const float4*>(&C0[(size_t)m * Hd + n0 + tx * 4]);
        float v0 = acc[i][0] + c4.x, v1 = acc[i][1] + c4.y;
        float v2 = acc[i][2] + c4.z, v3 = acc[i][3] + c4.w;
        float4 o;
        if (MODE == 2) {
            o.x = s4.x * sig_(v0); o.y = s4.y * sig_(v1);
            o.z = s4.z * sig_(v2); o.w = s4.w * sig_(v3);
        } else {
            o.x = sp_(v0); o.y = sp_(v1); o.z = sp_(v2); o.w = sp_(v3);
        }
        *reinterpret_cast<float4*>(&Out[(size_t)m * Hd + n0 + tx * 4]) = o;
    }
}

// Backward through hidden layer i:
//   n in [0,832):   dnext = (dcur @ SWz_i) * sigma(h_prev)
//   n in [832,1088): g (+)= dcur @ Wx_i[:, :256]     (FIRSTG: g = wx_out + ...)
template<bool FIRSTG>
__global__ void __launch_bounds__(NTHR) kbwd(
    const float* __restrict__ Dcur, const float* __restrict__ SWzL,
    const float* __restrict__ WxL, const float* __restrict__ Hprev,
    float* __restrict__ Dnext, const float* __restrict__ wx_out)
{
    __shared__ float As[2][BK][BM + 4];
    __shared__ float Bs[2][BK][BN];
    const int tid = threadIdx.x, tx = tid & 15, ty = tid >> 4;
    const int m0 = blockIdx.y * BM, n0 = blockIdx.x * BN;
    const bool gpath = (n0 >= Hd);

    float acc[8][4];
#pragma unroll
    for (int i = 0; i < 8; i++)
#pragma unroll
        for (int j = 0; j < 4; j++) acc[i][j] = 0.f;

    const float* Bm = gpath ? (WxL + (n0 - Hd)) : (SWzL + n0);
    mm_nn(acc, Dcur, Hd, Bm, Hd, Hd / BK, m0, tid, tx, ty, As, Bs);

    if (!gpath) {
#pragma unroll
        for (int i = 0; i < 8; i++) {
            int m = m0 + ty * 8 + i;
            const float4 h4 = *reinterpret_cast<const float4*>(&Hprev[(size_t)m * Hd + n0 + tx * 4]);
            float4 o;
            o.x = acc[i][0] * sig_from_h(h4.x);
            o.y = acc[i][1] * sig_from_h(h4.y);
            o.z = acc[i][2] * sig_from_h(h4.z);
            o.w = acc[i][3] * sig_from_h(h4.w);
            *reinterpret_cast<float4*>(&Dnext[(size_t)m * Hd + n0 + tx * 4]) = o;
        }
    } else {
        float* G = g_buf + O_G;
        const int col0 = (n0 - Hd) + tx * 4;
        float4 w4;
        if (FIRSTG) w4 = *reinterpret_cast<const float4*>(&wx_out[col0]);
#pragma unroll
        for (int i = 0; i < 8; i++) {
            int m = m0 + ty * 8 + i;
            size_t idx = (size_t)m * Zd + col0;
            float4 base = FIRSTG ? w4 : *reinterpret_cast<const float4*>(&G[idx]);
            float4 o;
            o.x = base.x + acc[i][0]; o.y = base.y + acc[i][1];
            o.z = base.z + acc[i][2]; o.w = base.w + acc[i][3];
            *reinterpret_cast<float4*>(&G[idx]) = o;
        }
    }
}

// Final backward: g += d0 @ W_in[:, :256], then fused Adam update of z.
__global__ void __launch_bounds__(NTHR) kbwdin(
    const float* __restrict__ Dcur, const float* __restrict__ W_in,
    float* __restrict__ Z, float bc1, float bc2)
{
    __shared__ float As[2][BK][BM + 4];
    __shared__ float Bs[2][BK][BN];
    const int tid = threadIdx.x, tx = tid & 15, ty = tid >> 4;
    const int m0 = blockIdx.y * BM, n0 = blockIdx.x * BN;

    float acc[8][4];
#pragma unroll
    for (int i = 0; i < 8; i++)
#pragma unroll
        for (int j = 0; j < 4; j++) acc[i][j] = 0.f;

    mm_nn(acc, Dcur, Hd, W_in + n0, Hd, Hd / BK, m0, tid, tx, ty, As, Bs);

    const float* G = g_buf + O_G;
    float* Mm = g_buf + O_M;
    float* Vv = g_buf + O_V;
    const int col0 = n0 + tx * 4;
#pragma unroll
    for (int i = 0; i < 8; i++) {
        int m = m0 + ty * 8 + i;
        size_t idx = (size_t)m * Zd + col0;
        float4 g4 = *reinterpret_cast<const float4*>(&G[idx]);
        float gt[4] = {g4.x + acc[i][0], g4.y + acc[i][1],
                       g4.z + acc[i][2], g4.w + acc[i][3]};
        float4 m4 = *reinterpret_cast<const float4*>(&Mm[idx]);
        float4 v4 = *reinterpret_cast<const float4*>(&Vv[idx]);
        float mm[4] = {0.9f * m4.x + 0.1f * gt[0], 0.9f * m4.y + 0.1f * gt[1],
                       0.9f * m4.z + 0.1f * gt[2], 0.9f * m4.w + 0.1f * gt[3]};
        float vv[4] = {0.999f * v4.x + 0.001f * gt[0] * gt[0],
                       0.999f * v4.y + 0.001f * gt[1] * gt[1],
                       0.999f * v4.z + 0.001f * gt[2] * gt[2],
                       0.999f * v4.w + 0.001f * gt[3] * gt[3]};
        *reinterpret_cast<float4*>(&Mm[idx]) = make_float4(mm[0], mm[1], mm[2], mm[3]);
        *reinterpret_cast<float4*>(&Vv[idx]) = make_float4(vv[0], vv[1], vv[2], vv[3]);
        float4 z4 = *reinterpret_cast<float4*>(&Z[idx]);
        z4.x -= 0.01f * (mm[0] * bc1) / (sqrtf(vv[0] * bc2) + 1e-8f);
        z4.y -= 0.01f * (mm[1] * bc1) / (sqrtf(vv[1] * bc2) + 1e-8f);
        z4.z -= 0.01f * (mm[2] * bc1) / (sqrtf(vv[2] * bc2) + 1e-8f);
        z4.w -= 0.01f * (mm[3] * bc1) / (sqrtf(vv[3] * bc2) + 1e-8f);
        *reinterpret_cast<float4*>(&Z[idx]) = z4;
    }
}

// ---------------------------------------------------------------------------
// Host driver (graph-capturable: kernel launches only)
// ---------------------------------------------------------------------------
extern "C" void kernel_launch(void* const* d_in, const int* in_sizes, int n_in,
                              void* d_out, int out_size)
{
    (void)in_sizes; (void)n_in; (void)out_size;
    const float* x      = (const float*)d_in[0];
    const float* u      = (const float*)d_in[1];
    const float* W_in   = (const float*)d_in[2];
    const float* b_in   = (const float*)d_in[3];
    const float* Wzs    = (const float*)d_in[4];
    const float* Wxs    = (const float*)d_in[5];
    const float* bs     = (const float*)d_in[6];
    const float* wz_out = (const float*)d_in[7];
    const float* wx_out = (const float*)d_in[8];
    float* z = (float*)d_out;   // z lives directly in the output buffer

    float* buf = nullptr;
    { void* p = nullptr; cudaGetSymbolAddress(&p, g_buf); buf = (float*)p; }
    float* SWZ = buf + O_SWZ;
    float* C   = buf + O_C;
    float* H0  = buf + O_H;
    float* H1  = buf + O_H + (size_t)BH;
    float* H2  = buf + O_H + 2ull * BH;
    float* DA  = buf + O_DA;
    float* DB  = buf + O_DB;

    dim3 blk(NTHR);

    kprep<<<4096, 512>>>(Wzs, wz_out, z);
    kpre<<<dim3(Hd / BN, Bsz / BM, 4), blk>>>(x, u, W_in, b_in, Wxs, bs);

    const dim3 gF(Hd / BN, Bsz / BM);               // 13 x 32
    const dim3 gB((Hd + Zd) / BN, Bsz / BM);        // 17 x 32
    const dim3 gI(Zd / BN, Bsz / BM);               // 4 x 32

    for (int t = 0; t < NSTEPS; t++) {
        // forward
        kfwd<0><<<gF, blk>>>(z, W_in, nullptr, nullptr, C, H0);
        kfwd<1><<<gF, blk>>>(H0, SWZ,            z, Wxs,             C + 1ull * BH, H1);
        kfwd<1><<<gF, blk>>>(H1, SWZ + 1ull * HH, z, Wxs + 1ull * HH, C + 2ull * BH, H2);
        kfwd<2><<<gF, blk>>>(H2, SWZ + 2ull * HH, z, Wxs + 2ull * HH, C + 3ull * BH, DA); // emits d3
        // backward
        kbwd<true ><<<gB, blk>>>(DA, SWZ + 2ull * HH, Wxs + 2ull * HH, H2, DB, wx_out);
        kbwd<false><<<gB, blk>>>(DB, SWZ + 1ull * HH, Wxs + 1ull * HH, H1, DA, wx_out);
        kbwd<false><<<gB, blk>>>(DA, SWZ,             Wxs,             H0, DB, wx_out);
        double p1 = 1.0, p2 = 1.0;
        for (int q = 0; q <= t; q++) { p1 *= 0.9; p2 *= 0.999; }
        float bc1 = (float)(1.0 / (1.0 - p1));
        float bc2 = (float)(1.0 / (1.0 - p2));
        kbwdin<<<gI, blk>>>(DB, W_in, z, bc1, bc2);
    }
}

// round 4
// speedup vs baseline: 2.1388x; 2.1388x over previous
#include <cuda_runtime.h>
#include <cuda_bf16.h>
#include <math.h>
#include <stdint.h>

// ---------------------------------------------------------------------------
// KoopmanPhiICNN encode, R4: bf16x3 (hi/lo split) tensor-core GEMMs via
// mma.sync.m16n8k16. All GEMMs TN with precomputed transposed weight copies.
// ---------------------------------------------------------------------------

#define Bsz 4096
#define Hd  832
#define Zd  256
#define BH  (Bsz*Hd)
#define HH  (Hd*Hd)
#define BZ  (Bsz*Zd)
#define NSTEPS 64

#define BM 128
#define BN 64
#define BKT 32
#define BK 16
#define NTHR 256

// ---- fp32 scratch ----
#define O_SWZO 0ull
#define O_C    (O_SWZO + 1024ull)
#define O_G    (O_C + 4ull*BH)
#define O_M    (O_G + (unsigned long long)BZ)
#define O_V    (O_M + (unsigned long long)BZ)
#define TOTALF (O_V + (unsigned long long)BZ)
__device__ __align__(16) float g_buf[TOTALF];

// ---- bf16 scratch (hi/lo pairs) ----
#define SZ_WINZ  (832ull*256ull)
#define SZ_WXZ   (3ull*832ull*256ull)
#define SZ_SWZ   (3ull*(unsigned long long)HH)
#define OB_WINZ_H  0ull
#define OB_WINZ_L  (OB_WINZ_H + SZ_WINZ)
#define OB_WXZ_H   (OB_WINZ_L + SZ_WINZ)
#define OB_WXZ_L   (OB_WXZ_H + SZ_WXZ)
#define OB_SWZF_H  (OB_WXZ_L + SZ_WXZ)
#define OB_SWZF_L  (OB_SWZF_H + SZ_SWZ)
#define OB_SWZT_H  (OB_SWZF_L + SZ_SWZ)
#define OB_SWZT_L  (OB_SWZT_H + SZ_SWZ)
#define OB_WXZT_H  (OB_SWZT_L + SZ_SWZ)
#define OB_WXZT_L  (OB_WXZT_H + SZ_WXZ)
#define OB_WINZT_H (OB_WXZT_L + SZ_WXZ)
#define OB_WINZT_L (OB_WINZT_H + SZ_WINZ)
#define OB_H_H     (OB_WINZT_L + SZ_WINZ)
#define OB_H_L     (OB_H_H + 3ull*BH)
#define OB_DA_H    (OB_H_L + 3ull*BH)
#define OB_DA_L    (OB_DA_H + (unsigned long long)BH)
#define OB_DB_H    (OB_DA_L + (unsigned long long)BH)
#define OB_DB_L    (OB_DB_H + (unsigned long long)BH)
#define OB_Z_H     (OB_DB_L + (unsigned long long)BH)
#define OB_Z_L     (OB_Z_H + (unsigned long long)BZ)
#define TOTALB     (OB_Z_L + (unsigned long long)BZ)
__device__ __align__(16) __nv_bfloat16 g_bf[TOTALB];

__device__ __forceinline__ float sp_(float x) {
    return fmaxf(x, 0.f) + log1pf(expf(-fabsf(x)));
}
__device__ __forceinline__ float sig_(float x) { return 1.f / (1.f + expf(-x)); }
__device__ __forceinline__ float sig_from_h(float h) { return -expm1f(-h); }

__device__ __forceinline__ void bsplit(float v, __nv_bfloat16& h, __nv_bfloat16& l) {
    __nv_bfloat16 hh = __float2bfloat16(v);
    h = hh;
    l = __float2bfloat16(v - __bfloat162float(hh));
}
__device__ __forceinline__ void split_store2(__nv_bfloat16* Ph, __nv_bfloat16* Pl,
                                             size_t idx, float v0, float v1) {
    __nv_bfloat16 h0, l0, h1, l1;
    bsplit(v0, h0, l0); bsplit(v1, h1, l1);
    *(__nv_bfloat162*)(Ph + idx) = __halves2bfloat162(h0, h1);
    *(__nv_bfloat162*)(Pl + idx) = __halves2bfloat162(l0, l1);
}

// ---------------------------------------------------------------------------
// TN tensor-core GEMM core: C[128,64] += A[128,K]*B[64,K]^T, bf16 hi/lo x3
// ---------------------------------------------------------------------------
#define SA 40
#define OFF_AH 0
#define OFF_AL (128*SA)
#define OFF_BH (2*128*SA)
#define OFF_BL (2*128*SA + 64*SA)
#define STAGE_H (2*128*SA + 2*64*SA)
#define SMEM_BYTES (2*2*STAGE_H)

__device__ __forceinline__ void ldsm4(uint32_t* r, uint32_t addr) {
    asm volatile("ldmatrix.sync.aligned.m8n8.x4.shared.b16 {%0,%1,%2,%3}, [%4];\n"
        : "=r"(r[0]), "=r"(r[1]), "=r"(r[2]), "=r"(r[3]) : "r"(addr));
}
__device__ __forceinline__ void mmab(float* c, const uint32_t* a, uint32_t b0, uint32_t b1) {
    asm volatile("mma.sync.aligned.m16n8k16.row.col.f32.bf16.bf16.f32 "
        "{%0,%1,%2,%3},{%4,%5,%6,%7},{%8,%9},{%0,%1,%2,%3};\n"
        : "+f"(c[0]), "+f"(c[1]), "+f"(c[2]), "+f"(c[3])
        : "r"(a[0]), "r"(a[1]), "r"(a[2]), "r"(a[3]), "r"(b0), "r"(b1));
}
__device__ __forceinline__ void cp16(uint32_t dst, const void* src) {
    asm volatile("cp.async.cg.shared.global [%0], [%1], 16;\n" :: "r"(dst), "l"(src));
}
__device__ __forceinline__ void cpcommit() { asm volatile("cp.async.commit_group;\n"); }
template<int N> __device__ __forceinline__ void cpwait() {
    asm volatile("cp.async.wait_group %0;\n" :: "n"(N));
}

__device__ __forceinline__ void ld_stage(uint32_t smst,
    const __nv_bfloat16* __restrict__ Ah, const __nv_bfloat16* __restrict__ Al, int lda,
    const __nv_bfloat16* __restrict__ Bh, const __nv_bfloat16* __restrict__ Bl, int ldb,
    int m0, int n0, int k0, int tid)
{
#pragma unroll
    for (int h = 0; h < 2; h++) {
        int ch = tid + h * 256;
        int row = ch >> 2, kc = ch & 3;
        size_t go = (size_t)(m0 + row) * lda + k0 + kc * 8;
        uint32_t so = smst + 2 * (OFF_AH + row * SA + kc * 8);
        cp16(so, Ah + go);
        cp16(so + 2 * (OFF_AL - OFF_AH), Al + go);
    }
    {
        int row = tid >> 2, kc = tid & 3;
        size_t go = (size_t)(n0 + row) * ldb + k0 + kc * 8;
        uint32_t so = smst + 2 * (OFF_BH + row * SA + kc * 8);
        cp16(so, Bh + go);
        cp16(so + 2 * (OFF_BL - OFF_BH), Bl + go);
    }
}

__device__ __forceinline__ void compute_stage(float acc[2][4][4], uint32_t smst,
                                              int lane, int wm, int wn)
{
#pragma unroll
    for (int kk = 0; kk < 2; kk++) {
        const int k16 = kk * 16;
        uint32_t a0h[4], a1h[4], a0l[4], a1l[4];
        {
            int arow = lane & 15;
            int akoff = k16 + ((lane >> 4) << 3);
            uint32_t ad = smst + 2 * ((wm + arow) * SA + akoff);
            ldsm4(a0h, ad);
            ldsm4(a1h, ad + 2 * 16 * SA);
            ldsm4(a0l, ad + 2 * OFF_AL);
            ldsm4(a1l, ad + 2 * (OFF_AL + 16 * SA));
        }
        uint32_t b0h[4], b1h[4], b0l[4], b1l[4];
        {
            int brow = ((lane >> 4) << 3) + (lane & 7);
            int bkoff = k16 + (((lane >> 3) & 1) << 3);
            uint32_t bd = smst + 2 * (OFF_BH + (wn + brow) * SA + bkoff);
            ldsm4(b0h, bd);
            ldsm4(b1h, bd + 2 * 16 * SA);
            ldsm4(b0l, bd + 2 * (OFF_BL - OFF_BH));
            ldsm4(b1l, bd + 2 * (OFF_BL - OFF_BH) + 2 * 16 * SA);
        }
#pragma unroll
        for (int mi = 0; mi < 2; mi++) {
            const uint32_t* Ahf = mi ? a1h : a0h;
            const uint32_t* Alf = mi ? a1l : a0l;
#pragma unroll
            for (int ni = 0; ni < 4; ni++) {
                const uint32_t* Bhf = (ni < 2) ? b0h : b1h;
                const uint32_t* Blf = (ni < 2) ? b0l : b1l;
                int h2 = (ni & 1) * 2;
                mmab(acc[mi][ni], Ahf, Bhf[h2], Bhf[h2 + 1]);
                mmab(acc[mi][ni], Ahf, Blf[h2], Blf[h2 + 1]);
                mmab(acc[mi][ni], Alf, Bhf[h2], Bhf[h2 + 1]);
            }
        }
    }
}

__device__ __forceinline__ void gemm_tn(float acc[2][4][4], uint32_t smbase,
    const __nv_bfloat16* Ah, const __nv_bfloat16* Al, int lda,
    const __nv_bfloat16* Bh, const __nv_bfloat16* Bl, int ldb,
    int kt, int m0, int n0, int tid, int lane, int wm, int wn)
{
    __syncthreads();
    ld_stage(smbase, Ah, Al, lda, Bh, Bl, ldb, m0, n0, 0, tid);
    cpcommit();
    for (int t = 0; t < kt; t++) {
        if (t + 1 < kt) {
            ld_stage(smbase + ((t + 1) & 1) * 2 * STAGE_H,
                     Ah, Al, lda, Bh, Bl, ldb, m0, n0, (t + 1) * BKT, tid);
            cpcommit();
            cpwait<1>();
        } else {
            cpwait<0>();
        }
        __syncthreads();
        compute_stage(acc, smbase + (t & 1) * 2 * STAGE_H, lane, wm, wn);
        __syncthreads();
    }
}

// ---------------------------------------------------------------------------
// fp32 SIMT kpre (runs once): c[s] = [x|u] @ W_s[:,256:]^T + bias_s
// ---------------------------------------------------------------------------
__device__ __forceinline__ void mm_compute(float acc[8][4],
    const float As[BK][BM + 4], const float Bs[BK][BN], int tx, int ty)
{
#pragma unroll
    for (int kk = 0; kk < BK; kk++) {
        float4 a0 = *reinterpret_cast<const float4*>(&As[kk][ty * 8]);
        float4 a1 = *reinterpret_cast<const float4*>(&As[kk][ty * 8 + 4]);
        float4 b  = *reinterpret_cast<const float4*>(&Bs[kk][tx * 4]);
        float av[8] = {a0.x, a0.y, a0.z, a0.w, a1.x, a1.y, a1.z, a1.w};
        float bv[4] = {b.x, b.y, b.z, b.w};
#pragma unroll
        for (int i = 0; i < 8; i++)
#pragma unroll
            for (int j = 0; j < 4; j++)
                acc[i][j] = fmaf(av[i], bv[j], acc[i][j]);
    }
}
__device__ __forceinline__ void st_nt(float As[BK][BM + 4], float Bs[BK][BN],
                                      int r, int c, float4 va0, float4 va1, float4 vb)
{
    As[c + 0][r] = va0.x; As[c + 1][r] = va0.y; As[c + 2][r] = va0.z; As[c + 3][r] = va0.w;
    As[c + 0][r + 64] = va1.x; As[c + 1][r + 64] = va1.y; As[c + 2][r + 64] = va1.z; As[c + 3][r + 64] = va1.w;
    Bs[c + 0][r] = vb.x; Bs[c + 1][r] = vb.y; Bs[c + 2][r] = vb.z; Bs[c + 3][r] = vb.w;
}

__global__ void __launch_bounds__(NTHR) kpre(
    const float* __restrict__ x, const float* __restrict__ u,
    const float* __restrict__ W_in, const float* __restrict__ b_in,
    const float* __restrict__ Wxs, const float* __restrict__ bs)
{
    __shared__ float As[2][BK][BM + 4];
    __shared__ float Bs[2][BK][BN];
    const int tid = threadIdx.x, tx = tid & 15, ty = tid >> 4;
    const int m0 = blockIdx.y * BM, n0 = blockIdx.x * BN;
    const int s = blockIdx.z;
    const float* W    = (s == 0) ? W_in : Wxs + (size_t)(s - 1) * HH;
    const float* bias = (s == 0) ? b_in : bs + (size_t)(s - 1) * Hd;
    float* Out = g_buf + O_C + (size_t)s * BH;

    float acc[8][4];
#pragma unroll
    for (int i = 0; i < 8; i++)
#pragma unroll
        for (int j = 0; j < 4; j++) acc[i][j] = 0.f;

    const int r = tid >> 2;
    const int c = (tid & 3) * 4;
    const int kt = 576 / BK;
    const float* Bp = W + (size_t)(n0 + r) * Hd + 256 + c;

    float4 va0, va1, vb;
    va0 = *reinterpret_cast<const float4*>(&x[(size_t)(m0 + r) * 512 + c]);
    va1 = *reinterpret_cast<const float4*>(&x[(size_t)(m0 + r + 64) * 512 + c]);
    vb  = *reinterpret_cast<const float4*>(Bp);
    __syncthreads();
    st_nt(As[0], Bs[0], r, c, va0, va1, vb);
    __syncthreads();

    for (int t = 0; t < kt; t++) {
        int buf = t & 1;
        if (t + 1 < kt) {
            int k = (t + 1) * BK + c;
            if (k < 512) {
                va0 = *reinterpret_cast<const float4*>(&x[(size_t)(m0 + r) * 512 + k]);
                va1 = *reinterpret_cast<const float4*>(&x[(size_t)(m0 + r + 64) * 512 + k]);
            } else {
                va0 = *reinterpret_cast<const float4*>(&u[(size_t)(m0 + r) * 64 + (k - 512)]);
                va1 = *reinterpret_cast<const float4*>(&u[(size_t)(m0 + r + 64) * 64 + (k - 512)]);
            }
            vb = *reinterpret_cast<const float4*>(Bp + (t + 1) * BK);
        }
        mm_compute(acc, As[buf], Bs[buf], tx, ty);
        if (t + 1 < kt) st_nt(As[buf ^ 1], Bs[buf ^ 1], r, c, va0, va1, vb);
        __syncthreads();
    }

    const float4 b4 = *reinterpret_cast<const float4*>(&bias[n0 + tx * 4]);
#pragma unroll
    for (int i = 0; i < 8; i++) {
        int m = m0 + ty * 8 + i;
        float4 o;
        o.x = acc[i][0] + b4.x; o.y = acc[i][1] + b4.y;
        o.z = acc[i][2] + b4.z; o.w = acc[i][3] + b4.w;
        *reinterpret_cast<float4*>(&Out[(size_t)m * Hd + n0 + tx * 4]) = o;
    }
}

// ---------------------------------------------------------------------------
// Prep: weight splits/transposes + state init
// ---------------------------------------------------------------------------
__global__ void kprep(const float* __restrict__ Wzs, const float* __restrict__ wz_out,
                      const float* __restrict__ W_in, const float* __restrict__ Wxs,
                      float* __restrict__ Z)
{
    __nv_bfloat16* bf = g_bf;
    float* SWZO = g_buf + O_SWZO;
    float* Mm = g_buf + O_M;
    float* Vv = g_buf + O_V;
    const int n = 3 * HH;
    for (int i = blockIdx.x * blockDim.x + threadIdx.x; i < n;
         i += gridDim.x * blockDim.x) {
        int l = i / HH, o = i - l * HH;
        int r = o / Hd, c = o - r * Hd;
        float w = sp_(Wzs[i]);
        bsplit(w, bf[OB_SWZF_H + i], bf[OB_SWZF_L + i]);
        size_t ti = (size_t)l * HH + (size_t)c * Hd + r;
        bsplit(w, bf[OB_SWZT_H + ti], bf[OB_SWZT_L + ti]);
        if (c < Zd) {
            float wx = Wxs[i];
            size_t zi = (size_t)l * (Hd * Zd) + (size_t)r * Zd + c;
            bsplit(wx, bf[OB_WXZ_H + zi], bf[OB_WXZ_L + zi]);
            size_t zt = (size_t)l * (Zd * Hd) + (size_t)c * Hd + r;
            bsplit(wx, bf[OB_WXZT_H + zt], bf[OB_WXZT_L + zt]);
            if (l == 0) {
                float wi = W_in[o];
                bsplit(wi, bf[OB_WINZ_H + (size_t)r * Zd + c],
                           bf[OB_WINZ_L + (size_t)r * Zd + c]);
                bsplit(wi, bf[OB_WINZT_H + (size_t)c * Hd + r],
                           bf[OB_WINZT_L + (size_t)c * Hd + r]);
            }
        }
        if (i < Hd) SWZO[i] = sp_(wz_out[i]);
        if (i < BZ) {
            Z[i] = 0.f; Mm[i] = 0.f; Vv[i] = 0.f;
            bf[OB_Z_H + i] = __float2bfloat16(0.f);
            bf[OB_Z_L + i] = __float2bfloat16(0.f);
        }
    }
}

// ---------------------------------------------------------------------------
// Forward: MODE 0 input layer, MODE 1 hidden, MODE 2 hidden+final (emits d3)
// ---------------------------------------------------------------------------
template<int MODE>
__global__ void __launch_bounds__(NTHR) kfwd(
    const __nv_bfloat16* __restrict__ A1h, const __nv_bfloat16* __restrict__ A1l,
    const __nv_bfloat16* __restrict__ B1h, const __nv_bfloat16* __restrict__ B1l,
    const __nv_bfloat16* __restrict__ A2h, const __nv_bfloat16* __restrict__ A2l,
    const __nv_bfloat16* __restrict__ B2h, const __nv_bfloat16* __restrict__ B2l,
    const float* __restrict__ C0,
    __nv_bfloat16* __restrict__ Oh, __nv_bfloat16* __restrict__ Ol)
{
    extern __shared__ __align__(16) char dsm[];
    uint32_t smbase = (uint32_t)__cvta_generic_to_shared(dsm);
    const int tid = threadIdx.x, lane = tid & 31, wid = tid >> 5;
    const int wm = (wid >> 1) * 32, wn = (wid & 1) * 32;
    const int m0 = blockIdx.y * BM, n0 = blockIdx.x * BN;

    float acc[2][4][4];
#pragma unroll
    for (int a = 0; a < 2; a++)
#pragma unroll
        for (int b = 0; b < 4; b++)
#pragma unroll
            for (int d = 0; d < 4; d++) acc[a][b][d] = 0.f;

    if (MODE == 0) {
        gemm_tn(acc, smbase, A1h, A1l, Zd, B1h, B1l, Zd, Zd / BKT, m0, n0, tid, lane, wm, wn);
    } else {
        gemm_tn(acc, smbase, A1h, A1l, Hd, B1h, B1l, Hd, Hd / BKT, m0, n0, tid, lane, wm, wn);
        gemm_tn(acc, smbase, A2h, A2l, Zd, B2h, B2l, Zd, Zd / BKT, m0, n0, tid, lane, wm, wn);
    }

    const int l4 = lane >> 2, l2 = (lane & 3) * 2;
#pragma unroll
    for (int mi = 0; mi < 2; mi++)
#pragma unroll
    for (int ni = 0; ni < 4; ni++) {
        int mA = m0 + wm + mi * 16 + l4;
        int n  = n0 + wn + ni * 8 + l2;
        size_t iA = (size_t)mA * Hd + n, iB = iA + 8ull * Hd;
        float2 cA = *(const float2*)(C0 + iA);
        float2 cB = *(const float2*)(C0 + iB);
        float v0 = acc[mi][ni][0] + cA.x, v1 = acc[mi][ni][1] + cA.y;
        float v2 = acc[mi][ni][2] + cB.x, v3 = acc[mi][ni][3] + cB.y;
        if (MODE == 2) {
            const float* SWZO = g_buf + O_SWZO;
            float2 s2 = *(const float2*)(SWZO + n);
            v0 = s2.x * sig_(v0); v1 = s2.y * sig_(v1);
            v2 = s2.x * sig_(v2); v3 = s2.y * sig_(v3);
        } else {
            v0 = sp_(v0); v1 = sp_(v1); v2 = sp_(v2); v3 = sp_(v3);
        }
        split_store2(Oh, Ol, iA, v0, v1);
        split_store2(Oh, Ol, iB, v2, v3);
    }
}

// ---------------------------------------------------------------------------
// Backward hidden layer: n<832 d path, n>=832 gradient path
// ---------------------------------------------------------------------------
template<bool FIRSTG>
__global__ void __launch_bounds__(NTHR) kbwd(
    const __nv_bfloat16* __restrict__ Dh, const __nv_bfloat16* __restrict__ Dl,
    const __nv_bfloat16* __restrict__ STh, const __nv_bfloat16* __restrict__ STl,
    const __nv_bfloat16* __restrict__ XTh, const __nv_bfloat16* __restrict__ XTl,
    const __nv_bfloat16* __restrict__ Hph, const __nv_bfloat16* __restrict__ Hpl,
    __nv_bfloat16* __restrict__ Oh, __nv_bfloat16* __restrict__ Ol,
    const float* __restrict__ wx_out)
{
    extern __shared__ __align__(16) char dsm[];
    uint32_t smbase = (uint32_t)__cvta_generic_to_shared(dsm);
    const int tid = threadIdx.x, lane = tid & 31, wid = tid >> 5;
    const int wm = (wid >> 1) * 32, wn = (wid & 1) * 32;
    const int m0 = blockIdx.y * BM, n0 = blockIdx.x * BN;
    const bool gpath = (n0 >= Hd);

    float acc[2][4][4];
#pragma unroll
    for (int a = 0; a < 2; a++)
#pragma unroll
        for (int b = 0; b < 4; b++)
#pragma unroll
            for (int d = 0; d < 4; d++) acc[a][b][d] = 0.f;

    gemm_tn(acc, smbase, Dh, Dl, Hd,
            gpath ? XTh : STh, gpath ? XTl : STl, Hd, Hd / BKT,
            m0, gpath ? (n0 - Hd) : n0, tid, lane, wm, wn);

    const int l4 = lane >> 2, l2 = (lane & 3) * 2;
    if (!gpath) {
#pragma unroll
        for (int mi = 0; mi < 2; mi++)
#pragma unroll
        for (int ni = 0; ni < 4; ni++) {
            int mA = m0 + wm + mi * 16 + l4;
            int n  = n0 + wn + ni * 8 + l2;
            size_t iA = (size_t)mA * Hd + n, iB = iA + 8ull * Hd;
            __nv_bfloat162 hhA = *(const __nv_bfloat162*)(Hph + iA);
            __nv_bfloat162 hlA = *(const __nv_bfloat162*)(Hpl + iA);
            __nv_bfloat162 hhB = *(const __nv_bfloat162*)(Hph + iB);
            __nv_bfloat162 hlB = *(const __nv_bfloat162*)(Hpl + iB);
            float d0 = acc[mi][ni][0] * sig_from_h(__bfloat162float(hhA.x) + __bfloat162float(hlA.x));
            float d1 = acc[mi][ni][1] * sig_from_h(__bfloat162float(hhA.y) + __bfloat162float(hlA.y));
            float d2 = acc[mi][ni][2] * sig_from_h(__bfloat162float(hhB.x) + __bfloat162float(hlB.x));
            float d3 = acc[mi][ni][3] * sig_from_h(__bfloat162float(hhB.y) + __bfloat162float(hlB.y));
            split_store2(Oh, Ol, iA, d0, d1);
            split_store2(Oh, Ol, iB, d2, d3);
        }
    } else {
        float* G = g_buf + O_G;
        const int nb = n0 - Hd;
#pragma unroll
        for (int mi = 0; mi < 2; mi++)
#pragma unroll
        for (int ni = 0; ni < 4; ni++) {
            int mA = m0 + wm + mi * 16 + l4;
            int np = nb + wn + ni * 8 + l2;
            size_t gA = (size_t)mA * Zd + np, gB = gA + 8ull * Zd;
            float2 bA, bB;
            if (FIRSTG) {
                float2 w2 = *(const float2*)(wx_out + np);
                bA = w2; bB = w2;
            } else {
                bA = *(const float2*)(G + gA);
                bB = *(const float2*)(G + gB);
            }
            float2 oA, oB;
            oA.x = bA.x + acc[mi][ni][0]; oA.y = bA.y + acc[mi][ni][1];
            oB.x = bB.x + acc[mi][ni][2]; oB.y = bB.y + acc[mi][ni][3];
            *(float2*)(G + gA) = oA;
            *(float2*)(G + gB) = oB;
        }
    }
}

// ---------------------------------------------------------------------------
// Final backward + Adam: g += d0 @ W_in[:, :256]^T-form, update z (fp32+bf16)
// ---------------------------------------------------------------------------
__global__ void __launch_bounds__(NTHR) kbwdin(
    const __nv_bfloat16* __restrict__ Dh, const __nv_bfloat16* __restrict__ Dl,
    const __nv_bfloat16* __restrict__ WTh, const __nv_bfloat16* __restrict__ WTl,
    float* __restrict__ Z, __nv_bfloat16* __restrict__ Zh, __nv_bfloat16* __restrict__ Zl,
    float bc1, float bc2)
{
    extern __shared__ __align__(16) char dsm[];
    uint32_t smbase = (uint32_t)__cvta_generic_to_shared(dsm);
    const int tid = threadIdx.x, lane = tid & 31, wid = tid >> 5;
    const int wm = (wid >> 1) * 32, wn = (wid & 1) * 32;
    const int m0 = blockIdx.y * BM, n0 = blockIdx.x * BN;

    float acc[2][4][4];
#pragma unroll
    for (int a = 0; a < 2; a++)
#pragma unroll
        for (int b = 0; b < 4; b++)
#pragma unroll
            for (int d = 0; d < 4; d++) acc[a][b][d] = 0.f;

    gemm_tn(acc, smbase, Dh, Dl, Hd, WTh, WTl, Hd, Hd / BKT,
            m0, n0, tid, lane, wm, wn);

    const float* G = g_buf + O_G;
    float* Mm = g_buf + O_M;
    float* Vv = g_buf + O_V;
    const int l4 = lane >> 2, l2 = (lane & 3) * 2;
#pragma unroll
    for (int mi = 0; mi < 2; mi++)
#pragma unroll
    for (int ni = 0; ni < 4; ni++) {
        int mA = m0 + wm + mi * 16 + l4;
        int np = n0 + wn + ni * 8 + l2;
        size_t idx[2];
        idx[0] = (size_t)mA * Zd + np;
        idx[1] = idx[0] + 8ull * Zd;
#pragma unroll
        for (int hh = 0; hh < 2; hh++) {
            size_t id = idx[hh];
            float g0 = G[id]     + acc[mi][ni][hh * 2 + 0];
            float g1 = G[id + 1] + acc[mi][ni][hh * 2 + 1];
            float2 m2 = *(const float2*)(Mm + id);
            float2 v2 = *(const float2*)(Vv + id);
            float nm0 = 0.9f * m2.x + 0.1f * g0;
            float nm1 = 0.9f * m2.y + 0.1f * g1;
            float nv0 = 0.999f * v2.x + 0.001f * g0 * g0;
            float nv1 = 0.999f * v2.y + 0.001f * g1 * g1;
            *(float2*)(Mm + id) = make_float2(nm0, nm1);
            *(float2*)(Vv + id) = make_float2(nv0, nv1);
            float2 z2 = *(const float2*)(Z + id);
            z2.x -= 0.01f * (nm0 * bc1) / (sqrtf(nv0 * bc2) + 1e-8f);
            z2.y -= 0.01f * (nm1 * bc1) / (sqrtf(nv1 * bc2) + 1e-8f);
            *(float2*)(Z + id) = z2;
            split_store2(Zh, Zl, id, z2.x, z2.y);
        }
    }
}

// ---------------------------------------------------------------------------
// Host driver
// ---------------------------------------------------------------------------
extern "C" void kernel_launch(void* const* d_in, const int* in_sizes, int n_in,
                              void* d_out, int out_size)
{
    (void)in_sizes; (void)n_in; (void)out_size;
    const float* x      = (const float*)d_in[0];
    const float* u      = (const float*)d_in[1];
    const float* W_in   = (const float*)d_in[2];
    const float* b_in   = (const float*)d_in[3];
    const float* Wzs    = (const float*)d_in[4];
    const float* Wxs    = (const float*)d_in[5];
    const float* bs     = (const float*)d_in[6];
    const float* wz_out = (const float*)d_in[7];
    const float* wx_out = (const float*)d_in[8];
    float* z = (float*)d_out;

    float* buf = nullptr;
    { void* p = nullptr; cudaGetSymbolAddress(&p, g_buf); buf = (float*)p; }
    __nv_bfloat16* bb = nullptr;
    { void* p = nullptr; cudaGetSymbolAddress(&p, g_bf); bb = (__nv_bfloat16*)p; }

    float* C = buf + O_C;

    static bool attr_done = false;
    if (!attr_done) {
        cudaFuncSetAttribute(kfwd<0>, cudaFuncAttributeMaxDynamicSharedMemorySize, SMEM_BYTES);
        cudaFuncSetAttribute(kfwd<1>, cudaFuncAttributeMaxDynamicSharedMemorySize, SMEM_BYTES);
        cudaFuncSetAttribute(kfwd<2>, cudaFuncAttributeMaxDynamicSharedMemorySize, SMEM_BYTES);
        cudaFuncSetAttribute(kbwd<true>,  cudaFuncAttributeMaxDynamicSharedMemorySize, SMEM_BYTES);
        cudaFuncSetAttribute(kbwd<false>, cudaFuncAttributeMaxDynamicSharedMemorySize, SMEM_BYTES);
        cudaFuncSetAttribute(kbwdin, cudaFuncAttributeMaxDynamicSharedMemorySize, SMEM_BYTES);
        attr_done = true;
    }

    dim3 blk(NTHR);
    kprep<<<2048, 512>>>(Wzs, wz_out, W_in, Wxs, z);
    kpre<<<dim3(Hd / BN, Bsz / BM, 4), blk>>>(x, u, W_in, b_in, Wxs, bs);

    const dim3 gF(Hd / BN, Bsz / BM);            // 13 x 32
    const dim3 gB((Hd + Zd) / BN, Bsz / BM);     // 17 x 32
    const dim3 gI(Zd / BN, Bsz / BM);            // 4 x 32

    __nv_bfloat16 *Zh = bb + OB_Z_H, *Zl = bb + OB_Z_L;
    __nv_bfloat16 *DAh = bb + OB_DA_H, *DAl = bb + OB_DA_L;
    __nv_bfloat16 *DBh = bb + OB_DB_H, *DBl = bb + OB_DB_L;

    for (int t = 0; t < NSTEPS; t++) {
        // forward
        kfwd<0><<<gF, blk, SMEM_BYTES>>>(
            Zh, Zl, bb + OB_WINZ_H, bb + OB_WINZ_L,
            nullptr, nullptr, nullptr, nullptr,
            C, bb + OB_H_H, bb + OB_H_L);
        for (int l = 0; l < 3; l++) {
            __nv_bfloat16* Ah = bb + OB_H_H + (size_t)l * BH;
            __nv_bfloat16* Al = bb + OB_H_L + (size_t)l * BH;
            __nv_bfloat16* Oh = (l < 2) ? bb + OB_H_H + (size_t)(l + 1) * BH : DAh;
            __nv_bfloat16* Ol = (l < 2) ? bb + OB_H_L + (size_t)(l + 1) * BH : DAl;
            if (l < 2)
                kfwd<1><<<gF, blk, SMEM_BYTES>>>(
                    Ah, Al, bb + OB_SWZF_H + (size_t)l * HH, bb + OB_SWZF_L + (size_t)l * HH,
                    Zh, Zl, bb + OB_WXZ_H + (size_t)l * (Hd * Zd), bb + OB_WXZ_L + (size_t)l * (Hd * Zd),
                    C + (size_t)(l + 1) * BH, Oh, Ol);
            else
                kfwd<2><<<gF, blk, SMEM_BYTES>>>(
                    Ah, Al, bb + OB_SWZF_H + (size_t)l * HH, bb + OB_SWZF_L + (size_t)l * HH,
                    Zh, Zl, bb + OB_WXZ_H + (size_t)l * (Hd * Zd), bb + OB_WXZ_L + (size_t)l * (Hd * Zd),
                    C + (size_t)(l + 1) * BH, Oh, Ol);
        }
        // backward: d3(DA) -> d2(DB) -> d1(DA) -> d0(DB)
        kbwd<true><<<gB, blk, SMEM_BYTES>>>(
            DAh, DAl,
            bb + OB_SWZT_H + 2ull * HH, bb + OB_SWZT_L + 2ull * HH,
            bb + OB_WXZT_H + 2ull * (Zd * Hd), bb + OB_WXZT_L + 2ull * (Zd * Hd),
            bb + OB_H_H + 2ull * BH, bb + OB_H_L + 2ull * BH,
            DBh, DBl, wx_out);
        kbwd<false><<<gB, blk, SMEM_BYTES>>>(
            DBh, DBl,
            bb + OB_SWZT_H + 1ull * HH, bb + OB_SWZT_L + 1ull * HH,
            bb + OB_WXZT_H + 1ull * (Zd * Hd), bb + OB_WXZT_L + 1ull * (Zd * Hd),
            bb + OB_H_H + 1ull * BH, bb + OB_H_L + 1ull * BH,
            DAh, DAl, wx_out);
        kbwd<false><<<gB, blk, SMEM_BYTES>>>(
            DAh, DAl,
            bb + OB_SWZT_H, bb + OB_SWZT_L,
            bb + OB_WXZT_H, bb + OB_WXZT_L,
            bb + OB_H_H, bb + OB_H_L,
            DBh, DBl, wx_out);
        double p1 = 1.0, p2 = 1.0;
        for (int q = 0; q <= t; q++) { p1 *= 0.9; p2 *= 0.999; }
        float bc1 = (float)(1.0 / (1.0 - p1));
        float bc2 = (float)(1.0 / (1.0 - p2));
        kbwdin<<<gI, blk, SMEM_BYTES>>>(
            DBh, DBl, bb + OB_WINZT_H, bb + OB_WINZT_L,
            z, Zh, Zl, bc1, bc2);
    }
}

// round 6
// speedup vs baseline: 2.4536x; 1.1472x over previous
#include <cuda_runtime.h>
#include <cuda_bf16.h>
#include <math.h>
#include <stdint.h>

// ---------------------------------------------------------------------------
// KoopmanPhiICNN encode, R6: bf16x3 (hi/lo split) mma.sync GEMMs.
// 3-stage cp.async pipeline, ONE __syncthreads per K-stage.
// (tcgen05 is unavailable: harness compiles PTX at compute_100, not 100a.)
// ---------------------------------------------------------------------------

#define Bsz 4096
#define Hd  832
#define Zd  256
#define BH  (Bsz*Hd)
#define HH  (Hd*Hd)
#define BZ  (Bsz*Zd)
#define NSTEPS 64

#define BM 128
#define BN 64
#define BKT 32
#define BK 16
#define NTHR 256
#define NSTAGE 3

// ---- fp32 scratch ----
#define O_SWZO 0ull
#define O_C    (O_SWZO + 1024ull)
#define O_G    (O_C + 4ull*BH)
#define O_M    (O_G + (unsigned long long)BZ)
#define O_V    (O_M + (unsigned long long)BZ)
#define TOTALF (O_V + (unsigned long long)BZ)
__device__ __align__(16) float g_buf[TOTALF];

// ---- bf16 scratch (hi/lo pairs) ----
#define SZ_WINZ  (832ull*256ull)
#define SZ_WXZ   (3ull*832ull*256ull)
#define SZ_SWZ   (3ull*(unsigned long long)HH)
#define OB_WINZ_H  0ull
#define OB_WINZ_L  (OB_WINZ_H + SZ_WINZ)
#define OB_WXZ_H   (OB_WINZ_L + SZ_WINZ)
#define OB_WXZ_L   (OB_WXZ_H + SZ_WXZ)
#define OB_SWZF_H  (OB_WXZ_L + SZ_WXZ)
#define OB_SWZF_L  (OB_SWZF_H + SZ_SWZ)
#define OB_SWZT_H  (OB_SWZF_L + SZ_SWZ)
#define OB_SWZT_L  (OB_SWZT_H + SZ_SWZ)
#define OB_WXZT_H  (OB_SWZT_L + SZ_SWZ)
#define OB_WXZT_L  (OB_WXZT_H + SZ_WXZ)
#define OB_WINZT_H (OB_WXZT_L + SZ_WXZ)
#define OB_WINZT_L (OB_WINZT_H + SZ_WINZ)
#define OB_H_H     (OB_WINZT_L + SZ_WINZ)
#define OB_H_L     (OB_H_H + 3ull*BH)
#define OB_DA_H    (OB_H_L + 3ull*BH)
#define OB_DA_L    (OB_DA_H + (unsigned long long)BH)
#define OB_DB_H    (OB_DA_L + (unsigned long long)BH)
#define OB_DB_L    (OB_DB_H + (unsigned long long)BH)
#define OB_Z_H     (OB_DB_L + (unsigned long long)BH)
#define OB_Z_L     (OB_Z_H + (unsigned long long)BZ)
#define TOTALB     (OB_Z_L + (unsigned long long)BZ)
__device__ __align__(16) __nv_bfloat16 g_bf[TOTALB];

__device__ __forceinline__ float sp_(float x) {
    return fmaxf(x, 0.f) + log1pf(expf(-fabsf(x)));
}
__device__ __forceinline__ float sig_(float x) { return 1.f / (1.f + expf(-x)); }
__device__ __forceinline__ float sig_from_h(float h) { return -expm1f(-h); }

__device__ __forceinline__ void bsplit(float v, __nv_bfloat16& h, __nv_bfloat16& l) {
    __nv_bfloat16 hh = __float2bfloat16(v);
    h = hh;
    l = __float2bfloat16(v - __bfloat162float(hh));
}
__device__ __forceinline__ void split_store2(__nv_bfloat16* Ph, __nv_bfloat16* Pl,
                                             size_t idx, float v0, float v1) {
    __nv_bfloat16 h0, l0, h1, l1;
    bsplit(v0, h0, l0); bsplit(v1, h1, l1);
    *(__nv_bfloat162*)(Ph + idx) = __halves2bfloat162(h0, h1);
    *(__nv_bfloat162*)(Pl + idx) = __halves2bfloat162(l0, l1);
}

// ---------------------------------------------------------------------------
// TN tensor-core GEMM core: C[128,64] += A[128,K]*B[64,K]^T, bf16 hi/lo x3
// 3-stage cp.async pipeline, one barrier per stage.
// ---------------------------------------------------------------------------
#define SA 40
#define OFF_AH 0
#define OFF_AL (128*SA)
#define OFF_BH (2*128*SA)
#define OFF_BL (2*128*SA + 64*SA)
#define STAGE_H (2*128*SA + 2*64*SA)        // 15360 halves = 30720 B
#define SMEM_BYTES (NSTAGE*2*STAGE_H)       // 92160 B

__device__ __forceinline__ void ldsm4(uint32_t* r, uint32_t addr) {
    asm volatile("ldmatrix.sync.aligned.m8n8.x4.shared.b16 {%0,%1,%2,%3}, [%4];\n"
        : "=r"(r[0]), "=r"(r[1]), "=r"(r[2]), "=r"(r[3]) : "r"(addr));
}
__device__ __forceinline__ void mmab(float* c, const uint32_t* a, uint32_t b0, uint32_t b1) {
    asm volatile("mma.sync.aligned.m16n8k16.row.col.f32.bf16.bf16.f32 "
        "{%0,%1,%2,%3},{%4,%5,%6,%7},{%8,%9},{%0,%1,%2,%3};\n"
        : "+f"(c[0]), "+f"(c[1]), "+f"(c[2]), "+f"(c[3])
        : "r"(a[0]), "r"(a[1]), "r"(a[2]), "r"(a[3]), "r"(b0), "r"(b1));
}
__device__ __forceinline__ void cp16(uint32_t dst, const void* src) {
    asm volatile("cp.async.cg.shared.global [%0], [%1], 16;\n" :: "r"(dst), "l"(src));
}
__device__ __forceinline__ void cpcommit() { asm volatile("cp.async.commit_group;\n"); }
template<int N> __device__ __forceinline__ void cpwait() {
    asm volatile("cp.async.wait_group %0;\n" :: "n"(N));
}

__device__ __forceinline__ void ld_stage(uint32_t smst,
    const __nv_bfloat16* __restrict__ Ah, const __nv_bfloat16* __restrict__ Al, int lda,
    const __nv_bfloat16* __restrict__ Bh, const __nv_bfloat16* __restrict__ Bl, int ldb,
    int m0, int n0, int k0, int tid)
{
#pragma unroll
    for (int h = 0; h < 2; h++) {
        int ch = tid + h * 256;
        int row = ch >> 2, kc = ch & 3;
        size_t go = (size_t)(m0 + row) * lda + k0 + kc * 8;
        uint32_t so = smst + 2 * (OFF_AH + row * SA + kc * 8);
        cp16(so, Ah + go);
        cp16(so + 2 * (OFF_AL - OFF_AH), Al + go);
    }
    {
        int row = tid >> 2, kc = tid & 3;
        size_t go = (size_t)(n0 + row) * ldb + k0 + kc * 8;
        uint32_t so = smst + 2 * (OFF_BH + row * SA + kc * 8);
        cp16(so, Bh + go);
        cp16(so + 2 * (OFF_BL - OFF_BH), Bl + go);
    }
}

__device__ __forceinline__ void compute_stage(float acc[2][4][4], uint32_t smst,
                                              int lane, int wm, int wn)
{
#pragma unroll
    for (int kk = 0; kk < 2; kk++) {
        const int k16 = kk * 16;
        uint32_t a0h[4], a1h[4], a0l[4], a1l[4];
        {
            int arow = lane & 15;
            int akoff = k16 + ((lane >> 4) << 3);
            uint32_t ad = smst + 2 * ((wm + arow) * SA + akoff);
            ldsm4(a0h, ad);
            ldsm4(a1h, ad + 2 * 16 * SA);
            ldsm4(a0l, ad + 2 * OFF_AL);
            ldsm4(a1l, ad + 2 * (OFF_AL + 16 * SA));
        }
        uint32_t b0h[4], b1h[4], b0l[4], b1l[4];
        {
            int brow = ((lane >> 4) << 3) + (lane & 7);
            int bkoff = k16 + (((lane >> 3) & 1) << 3);
            uint32_t bd = smst + 2 * (OFF_BH + (wn + brow) * SA + bkoff);
            ldsm4(b0h, bd);
            ldsm4(b1h, bd + 2 * 16 * SA);
            ldsm4(b0l, bd + 2 * (OFF_BL - OFF_BH));
            ldsm4(b1l, bd + 2 * (OFF_BL - OFF_BH) + 2 * 16 * SA);
        }
#pragma unroll
        for (int mi = 0; mi < 2; mi++) {
            const uint32_t* Ahf = mi ? a1h : a0h;
            const uint32_t* Alf = mi ? a1l : a0l;
#pragma unroll
            for (int ni = 0; ni < 4; ni++) {
                const uint32_t* Bhf = (ni < 2) ? b0h : b1h;
                const uint32_t* Blf = (ni < 2) ? b0l : b1l;
                int h2 = (ni & 1) * 2;
                mmab(acc[mi][ni], Ahf, Bhf[h2], Bhf[h2 + 1]);
                mmab(acc[mi][ni], Ahf, Blf[h2], Blf[h2 + 1]);
                mmab(acc[mi][ni], Alf, Bhf[h2], Bhf[h2 + 1]);
            }
        }
    }
}

// 3-stage pipeline, one __syncthreads per K-stage.
// Safety: the buffer written at iter t ((t+2)%3) was consumed in compute(t-1);
// this iter's barrier (post-wait) proves every warp finished compute(t-1).
__device__ __forceinline__ void gemm_tn(float acc[2][4][4], uint32_t smbase,
    const __nv_bfloat16* Ah, const __nv_bfloat16* Al, int lda,
    const __nv_bfloat16* Bh, const __nv_bfloat16* Bl, int ldb,
    int kt, int m0, int n0, int tid, int lane, int wm, int wn)
{
    __syncthreads();   // previous users of smem done
    ld_stage(smbase, Ah, Al, lda, Bh, Bl, ldb, m0, n0, 0, tid);
    cpcommit();
    if (kt > 1) ld_stage(smbase + 2 * STAGE_H, Ah, Al, lda, Bh, Bl, ldb, m0, n0, BKT, tid);
    cpcommit();        // always 2 prologue groups (2nd may be empty)

    for (int t = 0; t < kt; t++) {
        cpwait<1>();          // stage t resident (≤1 newer group outstanding)
        __syncthreads();
        compute_stage(acc, smbase + (t % 3) * 2 * STAGE_H, lane, wm, wn);
        if (t + 2 < kt)
            ld_stage(smbase + ((t + 2) % 3) * 2 * STAGE_H,
                     Ah, Al, lda, Bh, Bl, ldb, m0, n0, (t + 2) * BKT, tid);
        cpcommit();           // keep group count aligned (may be empty)
    }
}

// ---------------------------------------------------------------------------
// fp32 SIMT kpre (runs once): c[s] = [x|u] @ W_s[:,256:]^T + bias_s
// ---------------------------------------------------------------------------
__device__ __forceinline__ void mm_compute(float acc[8][4],
    const float As[BK][BM + 4], const float Bs[BK][BN], int tx, int ty)
{
#pragma unroll
    for (int kk = 0; kk < BK; kk++) {
        float4 a0 = *reinterpret_cast<const float4*>(&As[kk][ty * 8]);
        float4 a1 = *reinterpret_cast<const float4*>(&As[kk][ty * 8 + 4]);
        float4 b  = *reinterpret_cast<const float4*>(&Bs[kk][tx * 4]);
        float av[8] = {a0.x, a0.y, a0.z, a0.w, a1.x, a1.y, a1.z, a1.w};
        float bv[4] = {b.x, b.y, b.z, b.w};
#pragma unroll
        for (int i = 0; i < 8; i++)
#pragma unroll
            for (int j = 0; j < 4; j++)
                acc[i][j] = fmaf(av[i], bv[j], acc[i][j]);
    }
}
__device__ __forceinline__ void st_nt(float As[BK][BM + 4], float Bs[BK][BN],
                                      int r, int c, float4 va0, float4 va1, float4 vb)
{
    As[c + 0][r] = va0.x; As[c + 1][r] = va0.y; As[c + 2][r] = va0.z; As[c + 3][r] = va0.w;
    As[c + 0][r + 64] = va1.x; As[c + 1][r + 64] = va1.y; As[c + 2][r + 64] = va1.z; As[c + 3][r + 64] = va1.w;
    Bs[c + 0][r] = vb.x; Bs[c + 1][r] = vb.y; Bs[c + 2][r] = vb.z; Bs[c + 3][r] = vb.w;
}

__global__ void __launch_bounds__(NTHR) kpre(
    const float* __restrict__ x, const float* __restrict__ u,
    const float* __restrict__ W_in, const float* __restrict__ b_in,
    const float* __restrict__ Wxs, const float* __restrict__ bs)
{
    __shared__ float As[2][BK][BM + 4];
    __shared__ float Bs[2][BK][BN];
    const int tid = threadIdx.x, tx = tid & 15, ty = tid >> 4;
    const int m0 = blockIdx.y * BM, n0 = blockIdx.x * BN;
    const int s = blockIdx.z;
    const float* W    = (s == 0) ? W_in : Wxs + (size_t)(s - 1) * HH;
    const float* bias = (s == 0) ? b_in : bs + (size_t)(s - 1) * Hd;
    float* Out = g_buf + O_C + (size_t)s * BH;

    float acc[8][4];
#pragma unroll
    for (int i = 0; i < 8; i++)
#pragma unroll
        for (int j = 0; j < 4; j++) acc[i][j] = 0.f;

    const int r = tid >> 2;
    const int c = (tid & 3) * 4;
    const int kt = 576 / BK;
    const float* Bp = W + (size_t)(n0 + r) * Hd + 256 + c;

    float4 va0, va1, vb;
    va0 = *reinterpret_cast<const float4*>(&x[(size_t)(m0 + r) * 512 + c]);
    va1 = *reinterpret_cast<const float4*>(&x[(size_t)(m0 + r + 64) * 512 + c]);
    vb  = *reinterpret_cast<const float4*>(Bp);
    __syncthreads();
    st_nt(As[0], Bs[0], r, c, va0, va1, vb);
    __syncthreads();

    for (int t = 0; t < kt; t++) {
        int buf = t & 1;
        if (t + 1 < kt) {
            int k = (t + 1) * BK + c;
            if (k < 512) {
                va0 = *reinterpret_cast<const float4*>(&x[(size_t)(m0 + r) * 512 + k]);
                va1 = *reinterpret_cast<const float4*>(&x[(size_t)(m0 + r + 64) * 512 + k]);
            } else {
                va0 = *reinterpret_cast<const float4*>(&u[(size_t)(m0 + r) * 64 + (k - 512)]);
                va1 = *reinterpret_cast<const float4*>(&u[(size_t)(m0 + r + 64) * 64 + (k - 512)]);
            }
            vb = *reinterpret_cast<const float4*>(Bp + (t + 1) * BK);
        }
        mm_compute(acc, As[buf], Bs[buf], tx, ty);
        if (t + 1 < kt) st_nt(As[buf ^ 1], Bs[buf ^ 1], r, c, va0, va1, vb);
        __syncthreads();
    }

    const float4 b4 = *reinterpret_cast<const float4*>(&bias[n0 + tx * 4]);
#pragma unroll
    for (int i = 0; i < 8; i++) {
        int m = m0 + ty * 8 + i;
        float4 o;
        o.x = acc[i][0] + b4.x; o.y = acc[i][1] + b4.y;
        o.z = acc[i][2] + b4.z; o.w = acc[i][3] + b4.w;
        *reinterpret_cast<float4*>(&Out[(size_t)m * Hd + n0 + tx * 4]) = o;
    }
}

// ---------------------------------------------------------------------------
// Prep: weight splits/transposes + state init
// ---------------------------------------------------------------------------
__global__ void kprep(const float* __restrict__ Wzs, const float* __restrict__ wz_out,
                      const float* __restrict__ W_in, const float* __restrict__ Wxs,
                      float* __restrict__ Z)
{
    __nv_bfloat16* bf = g_bf;
    float* SWZO = g_buf + O_SWZO;
    float* Mm = g_buf + O_M;
    float* Vv = g_buf + O_V;
    const int n = 3 * HH;
    for (int i = blockIdx.x * blockDim.x + threadIdx.x; i < n;
         i += gridDim.x * blockDim.x) {
        int l = i / HH, o = i - l * HH;
        int r = o / Hd, c = o - r * Hd;
        float w = sp_(Wzs[i]);
        bsplit(w, bf[OB_SWZF_H + i], bf[OB_SWZF_L + i]);
        size_t ti = (size_t)l * HH + (size_t)c * Hd + r;
        bsplit(w, bf[OB_SWZT_H + ti], bf[OB_SWZT_L + ti]);
        if (c < Zd) {
            float wx = Wxs[i];
            size_t zi = (size_t)l * (Hd * Zd) + (size_t)r * Zd + c;
            bsplit(wx, bf[OB_WXZ_H + zi], bf[OB_WXZ_L + zi]);
            size_t zt = (size_t)l * (Zd * Hd) + (size_t)c * Hd + r;
            bsplit(wx, bf[OB_WXZT_H + zt], bf[OB_WXZT_L + zt]);
            if (l == 0) {
                float wi = W_in[o];
                bsplit(wi, bf[OB_WINZ_H + (size_t)r * Zd + c],
                           bf[OB_WINZ_L + (size_t)r * Zd + c]);
                bsplit(wi, bf[OB_WINZT_H + (size_t)c * Hd + r],
                           bf[OB_WINZT_L + (size_t)c * Hd + r]);
            }
        }
        if (i < Hd) SWZO[i] = sp_(wz_out[i]);
        if (i < BZ) {
            Z[i] = 0.f; Mm[i] = 0.f; Vv[i] = 0.f;
            bf[OB_Z_H + i] = __float2bfloat16(0.f);
            bf[OB_Z_L + i] = __float2bfloat16(0.f);
        }
    }
}

// ---------------------------------------------------------------------------
// Forward: MODE 0 input layer, MODE 1 hidden, MODE 2 hidden+final (emits d3)
// ---------------------------------------------------------------------------
template<int MODE>
__global__ void __launch_bounds__(NTHR, 2) kfwd(
    const __nv_bfloat16* __restrict__ A1h, const __nv_bfloat16* __restrict__ A1l,
    const __nv_bfloat16* __restrict__ B1h, const __nv_bfloat16* __restrict__ B1l,
    const __nv_bfloat16* __restrict__ A2h, const __nv_bfloat16* __restrict__ A2l,
    const __nv_bfloat16* __restrict__ B2h, const __nv_bfloat16* __restrict__ B2l,
    const float* __restrict__ C0,
    __nv_bfloat16* __restrict__ Oh, __nv_bfloat16* __restrict__ Ol)
{
    extern __shared__ __align__(16) char dsm[];
    uint32_t smbase = (uint32_t)__cvta_generic_to_shared(dsm);
    const int tid = threadIdx.x, lane = tid & 31, wid = tid >> 5;
    const int wm = (wid >> 1) * 32, wn = (wid & 1) * 32;
    const int m0 = blockIdx.y * BM, n0 = blockIdx.x * BN;

    float acc[2][4][4];
#pragma unroll
    for (int a = 0; a < 2; a++)
#pragma unroll
        for (int b = 0; b < 4; b++)
#pragma unroll
            for (int d = 0; d < 4; d++) acc[a][b][d] = 0.f;

    if (MODE == 0) {
        gemm_tn(acc, smbase, A1h, A1l, Zd, B1h, B1l, Zd, Zd / BKT, m0, n0, tid, lane, wm, wn);
    } else {
        gemm_tn(acc, smbase, A1h, A1l, Hd, B1h, B1l, Hd, Hd / BKT, m0, n0, tid, lane, wm, wn);
        gemm_tn(acc, smbase, A2h, A2l, Zd, B2h, B2l, Zd, Zd / BKT, m0, n0, tid, lane, wm, wn);
    }

    const int l4 = lane >> 2, l2 = (lane & 3) * 2;
#pragma unroll
    for (int mi = 0; mi < 2; mi++)
#pragma unroll
    for (int ni = 0; ni < 4; ni++) {
        int mA = m0 + wm + mi * 16 + l4;
        int n  = n0 + wn + ni * 8 + l2;
        size_t iA = (size_t)mA * Hd + n, iB = iA + 8ull * Hd;
        float2 cA = *(const float2*)(C0 + iA);
        float2 cB = *(const float2*)(C0 + iB);
        float v0 = acc[mi][ni][0] + cA.x, v1 = acc[mi][ni][1] + cA.y;
        float v2 = acc[mi][ni][2] + cB.x, v3 = acc[mi][ni][3] + cB.y;
        if (MODE == 2) {
            const float* SWZO = g_buf + O_SWZO;
            float2 s2 = *(const float2*)(SWZO + n);
            v0 = s2.x * sig_(v0); v1 = s2.y * sig_(v1);
            v2 = s2.x * sig_(v2); v3 = s2.y * sig_(v3);
        } else {
            v0 = sp_(v0); v1 = sp_(v1); v2 = sp_(v2); v3 = sp_(v3);
        }
        split_store2(Oh, Ol, iA, v0, v1);
        split_store2(Oh, Ol, iB, v2, v3);
    }
}

// ---------------------------------------------------------------------------
// Backward hidden layer: n<832 d path, n>=832 gradient path
// ---------------------------------------------------------------------------
template<bool FIRSTG>
__global__ void __launch_bounds__(NTHR, 2) kbwd(
    const __nv_bfloat16* __restrict__ Dh, const __nv_bfloat16* __restrict__ Dl,
    const __nv_bfloat16* __restrict__ STh, const __nv_bfloat16* __restrict__ STl,
    const __nv_bfloat16* __restrict__ XTh, const __nv_bfloat16* __restrict__ XTl,
    const __nv_bfloat16* __restrict__ Hph, const __nv_bfloat16* __restrict__ Hpl,
    __nv_bfloat16* __restrict__ Oh, __nv_bfloat16* __restrict__ Ol,
    const float* __restrict__ wx_out)
{
    extern __shared__ __align__(16) char dsm[];
    uint32_t smbase = (uint32_t)__cvta_generic_to_shared(dsm);
    const int tid = threadIdx.x, lane = tid & 31, wid = tid >> 5;
    const int wm = (wid >> 1) * 32, wn = (wid & 1) * 32;
    const int m0 = blockIdx.y * BM, n0 = blockIdx.x * BN;
    const bool gpath = (n0 >= Hd);

    float acc[2][4][4];
#pragma unroll
    for (int a = 0; a < 2; a++)
#pragma unroll
        for (int b = 0; b < 4; b++)
#pragma unroll
            for (int d = 0; d < 4; d++) acc[a][b][d] = 0.f;

    gemm_tn(acc, smbase, Dh, Dl, Hd,
            gpath ? XTh : STh, gpath ? XTl : STl, Hd, Hd / BKT,
            m0, gpath ? (n0 - Hd) : n0, tid, lane, wm, wn);

    const int l4 = lane >> 2, l2 = (lane & 3) * 2;
    if (!gpath) {
#pragma unroll
        for (int mi = 0; mi < 2; mi++)
#pragma unroll
        for (int ni = 0; ni < 4; ni++) {
            int mA = m0 + wm + mi * 16 + l4;
            int n  = n0 + wn + ni * 8 + l2;
            size_t iA = (size_t)mA * Hd + n, iB = iA + 8ull * Hd;
            __nv_bfloat162 hhA = *(const __nv_bfloat162*)(Hph + iA);
            __nv_bfloat162 hlA = *(const __nv_bfloat162*)(Hpl + iA);
            __nv_bfloat162 hhB = *(const __nv_bfloat162*)(Hph + iB);
            __nv_bfloat162 hlB = *(const __nv_bfloat162*)(Hpl + iB);
            float d0 = acc[mi][ni][0] * sig_from_h(__bfloat162float(hhA.x) + __bfloat162float(hlA.x));
            float d1 = acc[mi][ni][1] * sig_from_h(__bfloat162float(hhA.y) + __bfloat162float(hlA.y));
            float d2 = acc[mi][ni][2] * sig_from_h(__bfloat162float(hhB.x) + __bfloat162float(hlB.x));
            float d3 = acc[mi][ni][3] * sig_from_h(__bfloat162float(hhB.y) + __bfloat162float(hlB.y));
            split_store2(Oh, Ol, iA, d0, d1);
            split_store2(Oh, Ol, iB, d2, d3);
        }
    } else {
        float* G = g_buf + O_G;
        const int nb = n0 - Hd;
#pragma unroll
        for (int mi = 0; mi < 2; mi++)
#pragma unroll
        for (int ni = 0; ni < 4; ni++) {
            int mA = m0 + wm + mi * 16 + l4;
            int np = nb + wn + ni * 8 + l2;
            size_t gA = (size_t)mA * Zd + np, gB = gA + 8ull * Zd;
            float2 bA, bB;
            if (FIRSTG) {
                float2 w2 = *(const float2*)(wx_out + np);
                bA = w2; bB = w2;
            } else {
                bA = *(const float2*)(G + gA);
                bB = *(const float2*)(G + gB);
            }
            float2 oA, oB;
            oA.x = bA.x + acc[mi][ni][0]; oA.y = bA.y + acc[mi][ni][1];
            oB.x = bB.x + acc[mi][ni][2]; oB.y = bB.y + acc[mi][ni][3];
            *(float2*)(G + gA) = oA;
            *(float2*)(G + gB) = oB;
        }
    }
}

// ---------------------------------------------------------------------------
// Final backward + Adam
// ---------------------------------------------------------------------------
__global__ void __launch_bounds__(NTHR, 2) kbwdin(
    const __nv_bfloat16* __restrict__ Dh, const __nv_bfloat16* __restrict__ Dl,
    const __nv_bfloat16* __restrict__ WTh, const __nv_bfloat16* __restrict__ WTl,
    float* __restrict__ Z, __nv_bfloat16* __restrict__ Zh, __nv_bfloat16* __restrict__ Zl,
    float bc1, float bc2)
{
    extern __shared__ __align__(16) char dsm[];
    uint32_t smbase = (uint32_t)__cvta_generic_to_shared(dsm);
    const int tid = threadIdx.x, lane = tid & 31, wid = tid >> 5;
    const int wm = (wid >> 1) * 32, wn = (wid & 1) * 32;
    const int m0 = blockIdx.y * BM, n0 = blockIdx.x * BN;

    float acc[2][4][4];
#pragma unroll
    for (int a = 0; a < 2; a++)
#pragma unroll
        for (int b = 0; b < 4; b++)
#pragma unroll
            for (int d = 0; d < 4; d++) acc[a][b][d] = 0.f;

    gemm_tn(acc, smbase, Dh, Dl, Hd, WTh, WTl, Hd, Hd / BKT,
            m0, n0, tid, lane, wm, wn);

    const float* G = g_buf + O_G;
    float* Mm = g_buf + O_M;
    float* Vv = g_buf + O_V;
    const int l4 = lane >> 2, l2 = (lane & 3) * 2;
#pragma unroll
    for (int mi = 0; mi < 2; mi++)
#pragma unroll
    for (int ni = 0; ni < 4; ni++) {
        int mA = m0 + wm + mi * 16 + l4;
        int np = n0 + wn + ni * 8 + l2;
        size_t idx[2];
        idx[0] = (size_t)mA * Zd + np;
        idx[1] = idx[0] + 8ull * Zd;
#pragma unroll
        for (int hh = 0; hh < 2; hh++) {
            size_t id = idx[hh];
            float g0 = G[id]     + acc[mi][ni][hh * 2 + 0];
            float g1 = G[id + 1] + acc[mi][ni][hh * 2 + 1];
            float2 m2 = *(const float2*)(Mm + id);
            float2 v2 = *(const float2*)(Vv + id);
            float nm0 = 0.9f * m2.x + 0.1f * g0;
            float nm1 = 0.9f * m2.y + 0.1f * g1;
            float nv0 = 0.999f * v2.x + 0.001f * g0 * g0;
            float nv1 = 0.999f * v2.y + 0.001f * g1 * g1;
            *(float2*)(Mm + id) = make_float2(nm0, nm1);
            *(float2*)(Vv + id) = make_float2(nv0, nv1);
            float2 z2 = *(const float2*)(Z + id);
            z2.x -= 0.01f * (nm0 * bc1) / (sqrtf(nv0 * bc2) + 1e-8f);
            z2.y -= 0.01f * (nm1 * bc1) / (sqrtf(nv1 * bc2) + 1e-8f);
            *(float2*)(Z + id) = z2;
            split_store2(Zh, Zl, id, z2.x, z2.y);
        }
    }
}

// ---------------------------------------------------------------------------
// Host driver
// ---------------------------------------------------------------------------
extern "C" void kernel_launch(void* const* d_in, const int* in_sizes, int n_in,
                              void* d_out, int out_size)
{
    (void)in_sizes; (void)n_in; (void)out_size;
    const float* x      = (const float*)d_in[0];
    const float* u      = (const float*)d_in[1];
    const float* W_in   = (const float*)d_in[2];
    const float* b_in   = (const float*)d_in[3];
    const float* Wzs    = (const float*)d_in[4];
    const float* Wxs    = (const float*)d_in[5];
    const float* bs     = (const float*)d_in[6];
    const float* wz_out = (const float*)d_in[7];
    const float* wx_out = (const float*)d_in[8];
    float* z = (float*)d_out;

    float* buf = nullptr;
    { void* p = nullptr; cudaGetSymbolAddress(&p, g_buf); buf = (float*)p; }
    __nv_bfloat16* bb = nullptr;
    { void* p = nullptr; cudaGetSymbolAddress(&p, g_bf); bb = (__nv_bfloat16*)p; }

    float* C = buf + O_C;

    static bool attr_done = false;
    if (!attr_done) {
        cudaFuncSetAttribute(kfwd<0>, cudaFuncAttributeMaxDynamicSharedMemorySize, SMEM_BYTES);
        cudaFuncSetAttribute(kfwd<1>, cudaFuncAttributeMaxDynamicSharedMemorySize, SMEM_BYTES);
        cudaFuncSetAttribute(kfwd<2>, cudaFuncAttributeMaxDynamicSharedMemorySize, SMEM_BYTES);
        cudaFuncSetAttribute(kbwd<true>,  cudaFuncAttributeMaxDynamicSharedMemorySize, SMEM_BYTES);
        cudaFuncSetAttribute(kbwd<false>, cudaFuncAttributeMaxDynamicSharedMemorySize, SMEM_BYTES);
        cudaFuncSetAttribute(kbwdin, cudaFuncAttributeMaxDynamicSharedMemorySize, SMEM_BYTES);
        attr_done = true;
    }

    dim3 blk(NTHR);
    kprep<<<2048, 512>>>(Wzs, wz_out, W_in, Wxs, z);
    kpre<<<dim3(Hd / BN, Bsz / BM, 4), blk>>>(x, u, W_in, b_in, Wxs, bs);

    const dim3 gF(Hd / BN, Bsz / BM);            // 13 x 32
    const dim3 gB((Hd + Zd) / BN, Bsz / BM);     // 17 x 32
    const dim3 gI(Zd / BN, Bsz / BM);            // 4 x 32

    __nv_bfloat16 *Zh = bb + OB_Z_H, *Zl = bb + OB_Z_L;
    __nv_bfloat16 *DAh = bb + OB_DA_H, *DAl = bb + OB_DA_L;
    __nv_bfloat16 *DBh = bb + OB_DB_H, *DBl = bb + OB_DB_L;

    for (int t = 0; t < NSTEPS; t++) {
        kfwd<0><<<gF, blk, SMEM_BYTES>>>(
            Zh, Zl, bb + OB_WINZ_H, bb + OB_WINZ_L,
            (const __nv_bfloat16*)nullptr, (const __nv_bfloat16*)nullptr,
            (const __nv_bfloat16*)nullptr, (const __nv_bfloat16*)nullptr,
            C, bb + OB_H_H, bb + OB_H_L);
        for (int l = 0; l < 3; l++) {
            __nv_bfloat16* Ah = bb + OB_H_H + (size_t)l * BH;
            __nv_bfloat16* Al = bb + OB_H_L + (size_t)l * BH;
            __nv_bfloat16* Oh = (l < 2) ? bb + OB_H_H + (size_t)(l + 1) * BH : DAh;
            __nv_bfloat16* Ol = (l < 2) ? bb + OB_H_L + (size_t)(l + 1) * BH : DAl;
            if (l < 2)
                kfwd<1><<<gF, blk, SMEM_BYTES>>>(
                    Ah, Al, bb + OB_SWZF_H + (size_t)l * HH, bb + OB_SWZF_L + (size_t)l * HH,
                    Zh, Zl, bb + OB_WXZ_H + (size_t)l * (Hd * Zd), bb + OB_WXZ_L + (size_t)l * (Hd * Zd),
                    C + (size_t)(l + 1) * BH, Oh, Ol);
            else
                kfwd<2><<<gF, blk, SMEM_BYTES>>>(
                    Ah, Al, bb + OB_SWZF_H + (size_t)l * HH, bb + OB_SWZF_L + (size_t)l * HH,
                    Zh, Zl, bb + OB_WXZ_H + (size_t)l * (Hd * Zd), bb + OB_WXZ_L + (size_t)l * (Hd * Zd),
                    C + (size_t)(l + 1) * BH, Oh, Ol);
        }
        kbwd<true><<<gB, blk, SMEM_BYTES>>>(
            DAh, DAl,
            bb + OB_SWZT_H + 2ull * HH, bb + OB_SWZT_L + 2ull * HH,
            bb + OB_WXZT_H + 2ull * (Zd * Hd), bb + OB_WXZT_L + 2ull * (Zd * Hd),
            bb + OB_H_H + 2ull * BH, bb + OB_H_L + 2ull * BH,
            DBh, DBl, wx_out);
        kbwd<false><<<gB, blk, SMEM_BYTES>>>(
            DBh, DBl,
            bb + OB_SWZT_H + 1ull * HH, bb + OB_SWZT_L + 1ull * HH,
            bb + OB_WXZT_H + 1ull * (Zd * Hd), bb + OB_WXZT_L + 1ull * (Zd * Hd),
            bb + OB_H_H + 1ull * BH, bb + OB_H_L + 1ull * BH,
            DAh, DAl, wx_out);
        kbwd<false><<<gB, blk, SMEM_BYTES>>>(
            DAh, DAl,
            bb + OB_SWZT_H, bb + OB_SWZT_L,
            bb + OB_WXZT_H, bb + OB_WXZT_L,
            bb + OB_H_H, bb + OB_H_L,
            DBh, DBl, wx_out);
        double p1 = 1.0, p2 = 1.0;
        for (int q = 0; q <= t; q++) { p1 *= 0.9; p2 *= 0.999; }
        float bc1 = (float)(1.0 / (1.0 - p1));
        float bc2 = (float)(1.0 / (1.0 - p2));
        kbwdin<<<gI, blk, SMEM_BYTES>>>(
            DBh, DBl, bb + OB_WINZT_H, bb + OB_WINZT_L,
            z, Zh, Zl, bc1, bc2);
    }
}